// round 5
// baseline (speedup 1.0000x reference)
#include <cuda_runtime.h>
#include <math.h>
#include <stdint.h>

#define N_NODES 8192
#define N_BONDS 16384
#define EMBED 32
#define HIDDEN 256
#define DEPTH 10
#define NUM_GRAPHS 256

// ---------------- static device scratch ----------------
// A image: 4-bit {0,1}, fragment-ordered for mma.m16n8k32.s8.
// Block (mb 0..511, kc 0..63) = 1024B: [lane 32][kt 4][uint2].
//   word0 byte i: lo-nib = v(r, k0+i), hi-nib = v(r, k0+16+i)   (r = lane>>2, k0 = kc*128+kt*32+(lane&3)*4)
//   word1 byte i: same for row r+8.
__device__ __align__(16) uint8_t g_A4[(size_t)512 * 64 * 1024];  // 32MB
__device__ __align__(16) int8_t g_hq[(size_t)64 * N_NODES];      // [e(32 q1 | 32 q2)][j]
__device__ __align__(16) float g_h[N_NODES * EMBED];
__device__ __align__(16) float g_neip[8][N_NODES * EMBED];       // [kq*2+nw]
__device__ float g_deg[N_NODES];
__device__ float g_pool_sum[NUM_GRAPHS * EMBED];
__device__ float g_pool_cnt[NUM_GRAPHS];

#define S1 127.0f
#define S2 32258.0f  // 127*254

// ---------------- PTX helpers ----------------
__device__ __forceinline__ uint32_t smem_u32(const void* p) {
    uint32_t a;
    asm("{ .reg .u64 t; cvta.to.shared.u64 t, %1; cvt.u32.u64 %0, t; }" : "=r"(a) : "l"(p));
    return a;
}
__device__ __forceinline__ void cp16(uint32_t dst, const void* src) {
    asm volatile("cp.async.cg.shared.global [%0], [%1], 16;" :: "r"(dst), "l"(src));
}
__device__ __forceinline__ uint32_t lds32(uint32_t addr) {
    uint32_t v;
    asm volatile("ld.shared.b32 %0, [%1];" : "=r"(v) : "r"(addr));
    return v;
}
__device__ __forceinline__ void mma_s8(int* c, uint32_t a0, uint32_t a1,
                                       uint32_t a2, uint32_t a3,
                                       uint32_t b0, uint32_t b1) {
    asm volatile(
        "mma.sync.aligned.m16n8k32.row.col.s32.s8.s8.s32 "
        "{%0,%1,%2,%3}, {%4,%5,%6,%7}, {%8,%9}, {%0,%1,%2,%3};"
        : "+r"(c[0]), "+r"(c[1]), "+r"(c[2]), "+r"(c[3])
        : "r"(a0), "r"(a1), "r"(a2), "r"(a3), "r"(b0), "r"(b1));
}

// ---------------- init ----------------
__global__ void k_init(const int* __restrict__ af, const int* __restrict__ bf,
                       const float* __restrict__ atab, const float* __restrict__ btab,
                       float* __restrict__ out) {
    int idx = blockIdx.x * 256 + threadIdx.x;
    if (idx < N_BONDS * EMBED)
        out[N_NODES * EMBED + idx] = btab[bf[idx >> 5] * EMBED + (idx & 31)];
    if (idx < N_NODES * EMBED)
        g_h[idx] = atab[af[idx >> 5] * EMBED + (idx & 31)];
    if (idx < N_NODES) g_deg[idx] = 0.f;
    if (idx < NUM_GRAPHS * EMBED) g_pool_sum[idx] = 0.f;
    if (idx < NUM_GRAPHS) g_pool_cnt[idx] = 0.f;
}

// ---------------- adjacency -> 4-bit fragment-ordered image + degree ----------------
__global__ void __launch_bounds__(256) k_convA(const int* __restrict__ adj) {
    int t = threadIdx.x, lane = t & 31, w = t >> 5;
    int mb = blockIdx.x;
    int kc = blockIdx.y * 8 + w;
    int r = lane >> 2, kqo = (lane & 3) * 4;
    int row0 = mb * 16;
    uint8_t* dst = g_A4 + (((size_t)mb * 64 + kc) * 1024) + (size_t)lane * 32;
    int cnt0 = 0, cnt8 = 0;
#pragma unroll
    for (int kt = 0; kt < 4; kt++) {
        int k0 = kc * 128 + kt * 32 + kqo;
        int4 x0 = *(const int4*)&adj[(size_t)(row0 + r) * N_NODES + k0];
        int4 x1 = *(const int4*)&adj[(size_t)(row0 + r) * N_NODES + k0 + 16];
        int4 y0 = *(const int4*)&adj[(size_t)(row0 + r + 8) * N_NODES + k0];
        int4 y1 = *(const int4*)&adj[(size_t)(row0 + r + 8) * N_NODES + k0 + 16];
        uint32_t ax0 = (x0.x != 0), ax1 = (x0.y != 0), ax2 = (x0.z != 0), ax3 = (x0.w != 0);
        uint32_t bx0 = (x1.x != 0), bx1 = (x1.y != 0), bx2 = (x1.z != 0), bx3 = (x1.w != 0);
        uint32_t ay0 = (y0.x != 0), ay1 = (y0.y != 0), ay2 = (y0.z != 0), ay3 = (y0.w != 0);
        uint32_t by0 = (y1.x != 0), by1 = (y1.y != 0), by2 = (y1.z != 0), by3 = (y1.w != 0);
        cnt0 += ax0 + ax1 + ax2 + ax3 + bx0 + bx1 + bx2 + bx3;
        cnt8 += ay0 + ay1 + ay2 + ay3 + by0 + by1 + by2 + by3;
        uint32_t w0 = ax0 | (bx0 << 4) | (ax1 << 8) | (bx1 << 12) |
                      (ax2 << 16) | (bx2 << 20) | (ax3 << 24) | (bx3 << 28);
        uint32_t w1 = ay0 | (by0 << 4) | (ay1 << 8) | (by1 << 12) |
                      (ay2 << 16) | (by2 << 20) | (ay3 << 24) | (by3 << 28);
        *(uint2*)(dst + kt * 8) = make_uint2(w0, w1);
    }
    cnt0 += __shfl_down_sync(0xffffffffu, cnt0, 2, 4);
    cnt0 += __shfl_down_sync(0xffffffffu, cnt0, 1, 4);
    cnt8 += __shfl_down_sync(0xffffffffu, cnt8, 2, 4);
    cnt8 += __shfl_down_sync(0xffffffffu, cnt8, 1, 4);
    if ((lane & 3) == 0) {
        atomicAdd(&g_deg[row0 + r], (float)cnt0);
        atomicAdd(&g_deg[row0 + r + 8], (float)cnt8);
    }
}

// ---------------- initial h -> two-level int8 B image ----------------
__global__ void k_quant0() {
    int idx = blockIdx.x * 256 + threadIdx.x;  // 32*8192
    int e = idx >> 13, j = idx & 8191;
    float h = g_h[j * 32 + e];
    float q1 = rintf(h * S1);
    float q2 = rintf((h - q1 * (1.0f / S1)) * S2);
    g_hq[(size_t)e * 8192 + j] = (int8_t)q1;
    g_hq[(size_t)(32 + e) * 8192 + j] = (int8_t)q2;
}

// ---------------- nei partials = A @ [q1 | q2] via mma.sync s8 ----------------
// grid (64 mtiles, 4 kquarters), 256 threads = 8 warps (4m x 2n).
#define NEI_PITCH 144
#define NEI_STAGE_B (64 * NEI_PITCH)  // 9216
#define NEI_SMEM (4 * NEI_STAGE_B)
#define NEI_CHUNKS 16
#define NIBM 0x0F0F0F0Fu
__global__ void __launch_bounds__(256, 2) k_neimma() {
    extern __shared__ uint8_t smem[];
    uint32_t sb = smem_u32(smem);
    int t = threadIdx.x, lane = t & 31, w = t >> 5;
    int mw = w & 3, nw = w >> 2;
    int mtile = blockIdx.x, kq = blockIdx.y;

    const uint8_t* Abase = g_A4 +
        ((size_t)((mtile * 8 + mw * 2) * 64 + kq * 16)) * 1024 + (size_t)lane * 32;
    const int8_t* Bglob = g_hq + (size_t)kq * 2048;

#define LOADB(c, s)                                                             \
    {                                                                           \
        uint32_t dstb = sb + (s) * NEI_STAGE_B;                                 \
        const int8_t* srcb = Bglob + (size_t)(c) * 128;                         \
        _Pragma("unroll")                                                       \
        for (int i = 0; i < 2; i++) {                                           \
            int idx = t + i * 256;                                              \
            int e = idx >> 3, cg = idx & 7;                                     \
            cp16(dstb + e * NEI_PITCH + cg * 16,                                \
                 srcb + (size_t)e * 8192 + cg * 16);                            \
        }                                                                       \
        asm volatile("cp.async.commit_group;");                                 \
    }

    LOADB(0, 0);
    LOADB(1, 1);
    LOADB(2, 2);

    int acc[2][4][4];
#pragma unroll
    for (int mt = 0; mt < 2; mt++)
#pragma unroll
        for (int p = 0; p < 4; p++)
#pragma unroll
            for (int i = 0; i < 4; i++) acc[mt][p][i] = 0;

    int cfs = lane >> 2, rfs = lane & 3;

    for (int c = 0; c < NEI_CHUNKS; c++) {
        uint4 aw[2][2];
#pragma unroll
        for (int mt = 0; mt < 2; mt++) {
            const uint4* p4 = (const uint4*)(Abase + (size_t)mt * 65536 + (size_t)c * 1024);
            aw[mt][0] = p4[0];
            aw[mt][1] = p4[1];
        }
        asm volatile("cp.async.wait_group 2;");
        __syncthreads();
        uint32_t sbase = sb + (c & 3) * NEI_STAGE_B;
#pragma unroll
        for (int kt = 0; kt < 4; kt++) {
            uint32_t b0[4], b1[4];
#pragma unroll
            for (int p = 0; p < 4; p++) {
                uint32_t addr = sbase + (uint32_t)(nw * 32 + p * 8 + cfs) * NEI_PITCH +
                                kt * 32 + rfs * 4;
                b0[p] = lds32(addr);
                b1[p] = lds32(addr + 16);
            }
#pragma unroll
            for (int mt = 0; mt < 2; mt++) {
                uint4 q = aw[mt][kt >> 1];
                uint32_t w0 = (kt & 1) ? q.z : q.x;
                uint32_t w1 = (kt & 1) ? q.w : q.y;
                uint32_t a0 = w0 & NIBM;
                uint32_t a2 = (w0 >> 4) & NIBM;
                uint32_t a1 = w1 & NIBM;
                uint32_t a3 = (w1 >> 4) & NIBM;
                mma_s8(acc[mt][0], a0, a1, a2, a3, b0[0], b1[0]);
                mma_s8(acc[mt][1], a0, a1, a2, a3, b0[1], b1[1]);
                mma_s8(acc[mt][2], a0, a1, a2, a3, b0[2], b1[2]);
                mma_s8(acc[mt][3], a0, a1, a2, a3, b0[3], b1[3]);
            }
        }
        __syncthreads();
        if (c + 3 < NEI_CHUNKS) LOADB(c + 3, (c + 3) & 3);
    }

    float scale = nw ? (1.0f / S2) : (1.0f / S1);
    float* base = g_neip[kq * 2 + nw];
    int r = lane >> 2, c0 = (lane & 3) * 2;
#pragma unroll
    for (int mt = 0; mt < 2; mt++) {
        int node0 = mtile * 128 + mw * 32 + mt * 16 + r;
#pragma unroll
        for (int p = 0; p < 4; p++) {
            int col = p * 8 + c0;
            *(float2*)&base[(size_t)node0 * 32 + col] =
                make_float2((float)acc[mt][p][0] * scale, (float)acc[mt][p][1] * scale);
            *(float2*)&base[(size_t)(node0 + 8) * 32 + col] =
                make_float2((float)acc[mt][p][2] * scale, (float)acc[mt][p][3] * scale);
        }
    }
#undef LOADB
}

// ---------------- fused msg + GRU + int8 requant ----------------
#define WBUF_FLOATS 26112
#define MSGRU_SMEM_BYTES ((64 * 68 + 64 * 256 + WBUF_FLOATS + 32 * 102) * 4 + 64 * 72)
__global__ void __launch_bounds__(256) k_msgru(const float* __restrict__ Wd,
                                               const float* __restrict__ bd,
                                               const float* __restrict__ Wih,
                                               const float* __restrict__ Whh,
                                               const float* __restrict__ bih,
                                               const float* __restrict__ bhh) {
    extern __shared__ float sm[];
    float* x_s = sm;                       // [64][68]
    float* msg_s = x_s + 64 * 68;          // [64][256]
    float* wbuf = msg_s + 64 * 256;        // phase-shared weight buffer
    float* whh_s = wbuf + WBUF_FLOATS;     // [32][102]
    char* q_s = (char*)(whh_s + 32 * 102); // [64][72]
    int row0 = blockIdx.x * 64;
    int t = threadIdx.x;

    // stage x = [h | nei_mean]
    for (int idx = t; idx < 64 * EMBED; idx += 256) {
        int r = idx >> 5, e = idx & 31;
        int node = row0 + r;
        float invd = 1.0f / fmaxf(g_deg[node], 1.0f);
        int o = node * 32 + e;
        float s = g_neip[0][o] + g_neip[1][o] + g_neip[2][o] + g_neip[3][o] +
                  g_neip[4][o] + g_neip[5][o] + g_neip[6][o] + g_neip[7][o];
        x_s[r * 68 + e] = g_h[node * EMBED + e];
        x_s[r * 68 + 32 + e] = s * invd;
    }
    for (int idx = t; idx < HIDDEN * 64; idx += 256) {
        int o = idx >> 6, k = idx & 63;
        wbuf[k * 260 + o] = Wd[idx];
    }
    __syncthreads();

    // phase 1: msg -> msg_s
    {
        int rb = (t >> 5) * 8;
        int obA = (t & 31) * 4;
        int obB = 128 + obA;
        float acc[8][8];
#pragma unroll
        for (int i = 0; i < 8; i++)
#pragma unroll
            for (int j = 0; j < 8; j++) acc[i][j] = 0.f;
        for (int k = 0; k < 64; k++) {
            float4 wA = *(const float4*)&wbuf[k * 260 + obA];
            float4 wB = *(const float4*)&wbuf[k * 260 + obB];
#pragma unroll
            for (int i = 0; i < 8; i++) {
                float x = x_s[(rb + i) * 68 + k];
                acc[i][0] = fmaf(x, wA.x, acc[i][0]);
                acc[i][1] = fmaf(x, wA.y, acc[i][1]);
                acc[i][2] = fmaf(x, wA.z, acc[i][2]);
                acc[i][3] = fmaf(x, wA.w, acc[i][3]);
                acc[i][4] = fmaf(x, wB.x, acc[i][4]);
                acc[i][5] = fmaf(x, wB.y, acc[i][5]);
                acc[i][6] = fmaf(x, wB.z, acc[i][6]);
                acc[i][7] = fmaf(x, wB.w, acc[i][7]);
            }
        }
        float4 bA = *(const float4*)&bd[obA];
        float4 bB = *(const float4*)&bd[obB];
#pragma unroll
        for (int i = 0; i < 8; i++) {
            int node = row0 + rb + i;
            float hn = g_deg[node] > 0.f ? 1.f : 0.f;
            float4 oA, oB;
            oA.x = (acc[i][0] + bA.x) * hn; oA.y = (acc[i][1] + bA.y) * hn;
            oA.z = (acc[i][2] + bA.z) * hn; oA.w = (acc[i][3] + bA.w) * hn;
            oB.x = (acc[i][4] + bB.x) * hn; oB.y = (acc[i][5] + bB.y) * hn;
            oB.z = (acc[i][6] + bB.z) * hn; oB.w = (acc[i][7] + bB.w) * hn;
            *(float4*)&msg_s[(rb + i) * 256 + obA] = oA;
            *(float4*)&msg_s[(rb + i) * 256 + obB] = oB;
        }
    }
    __syncthreads();

    for (int idx = t; idx < 96 * HIDDEN; idx += 256) {
        int g = idx >> 8, k = idx & 255;
        wbuf[k * 102 + g] = Wih[idx];
    }
    for (int idx = t; idx < 96 * EMBED; idx += 256) {
        int g = idx >> 5, k = idx & 31;
        whh_s[k * 102 + g] = Whh[idx];
    }
    __syncthreads();

    // phase 2: GRU gates in registers + requant to q_s
    {
        int e = t & 31;
        int rb = (t >> 5) * 8;
        float gi[8][3], gh[8][3];
#pragma unroll
        for (int i = 0; i < 8; i++) {
            gi[i][0] = gi[i][1] = gi[i][2] = 0.f;
            gh[i][0] = gh[i][1] = gh[i][2] = 0.f;
        }
        for (int k = 0; k < HIDDEN; k++) {
            float w0 = wbuf[k * 102 + e];
            float w1 = wbuf[k * 102 + 32 + e];
            float w2 = wbuf[k * 102 + 64 + e];
#pragma unroll
            for (int i = 0; i < 8; i++) {
                float m = msg_s[(rb + i) * 256 + k];
                gi[i][0] = fmaf(m, w0, gi[i][0]);
                gi[i][1] = fmaf(m, w1, gi[i][1]);
                gi[i][2] = fmaf(m, w2, gi[i][2]);
            }
        }
        for (int k = 0; k < EMBED; k++) {
            float w0 = whh_s[k * 102 + e];
            float w1 = whh_s[k * 102 + 32 + e];
            float w2 = whh_s[k * 102 + 64 + e];
#pragma unroll
            for (int i = 0; i < 8; i++) {
                float hv = x_s[(rb + i) * 68 + k];
                gh[i][0] = fmaf(hv, w0, gh[i][0]);
                gh[i][1] = fmaf(hv, w1, gh[i][1]);
                gh[i][2] = fmaf(hv, w2, gh[i][2]);
            }
        }
        float bi0 = bih[e], bi1 = bih[32 + e], bi2 = bih[64 + e];
        float bh0 = bhh[e], bh1 = bhh[32 + e], bh2 = bhh[64 + e];
#pragma unroll
        for (int i = 0; i < 8; i++) {
            float rg = 1.f / (1.f + expf(-((gi[i][0] + bi0) + (gh[i][0] + bh0))));
            float z  = 1.f / (1.f + expf(-((gi[i][1] + bi1) + (gh[i][1] + bh1))));
            float n  = tanhf((gi[i][2] + bi2) + rg * (gh[i][2] + bh2));
            float hp = x_s[(rb + i) * 68 + e];
            float hnew = (1.f - z) * n + z * hp;
            int node = row0 + rb + i;
            g_h[(size_t)node * EMBED + e] = hnew;
            float q1 = rintf(hnew * S1);
            float q2 = rintf((hnew - q1 * (1.0f / S1)) * S2);
            q_s[(rb + i) * 72 + e] = (char)(int)q1;
            q_s[(rb + i) * 72 + 32 + e] = (char)(int)q2;
        }
    }
    __syncthreads();

    // copy q_s (transposed) to g_hq
    {
        int e = t >> 2;
        int n0 = (t & 3) << 4;
        uint32_t v[4];
#pragma unroll
        for (int g2 = 0; g2 < 4; g2++) {
            uint32_t b = 0;
#pragma unroll
            for (int n = 0; n < 4; n++)
                b |= ((uint32_t)(uint8_t)q_s[(n0 + g2 * 4 + n) * 72 + e]) << (n * 8);
            v[g2] = b;
        }
        *(uint4*)&g_hq[(size_t)e * 8192 + row0 + n0] = make_uint4(v[0], v[1], v[2], v[3]);
    }
}

// ---------------- pooling ----------------
__global__ void k_pool(const int* __restrict__ bidx, float* __restrict__ out) {
    int idx = blockIdx.x * 256 + threadIdx.x;
    if (idx < N_NODES * EMBED) {
        int n = idx >> 5, e = idx & 31;
        float v = g_h[idx];
        out[idx] = v;
        int b = bidx[n];
        atomicAdd(&g_pool_sum[b * EMBED + e], v);
        if (e == 0) atomicAdd(&g_pool_cnt[b], 1.0f);
    }
}

__global__ void __launch_bounds__(256) k_graph(const float* __restrict__ pW,
                                               const float* __restrict__ pb,
                                               float* __restrict__ out) {
    __shared__ float mean[EMBED];
    __shared__ float Ws[EMBED * HIDDEN];
    int b = blockIdx.x;
    int t = threadIdx.x;
    for (int idx = t; idx < HIDDEN * EMBED; idx += 256) {
        int o = idx >> 5, e = idx & 31;
        Ws[e * HIDDEN + o] = pW[idx];
    }
    if (t < EMBED) {
        float cnt = g_pool_cnt[b];
        mean[t] = cnt > 0.f ? g_pool_sum[b * EMBED + t] / cnt : 0.f;
    }
    __syncthreads();
    float acc = pb[t];
#pragma unroll
    for (int e = 0; e < EMBED; e++) acc = fmaf(mean[e], Ws[e * HIDDEN + t], acc);
    out[(size_t)(N_NODES * EMBED + N_BONDS * EMBED) + b * HIDDEN + t] = acc;
}

// ---------------- launch ----------------
extern "C" void kernel_launch(void* const* d_in, const int* in_sizes, int n_in,
                              void* d_out, int out_size) {
    const int* af    = (const int*)d_in[0];
    const int* bf    = (const int*)d_in[1];
    const int* adj   = (const int*)d_in[2];
    const int* bidx  = (const int*)d_in[3];
    const float* atab = (const float*)d_in[4];
    const float* btab = (const float*)d_in[5];
    const float* msgW = (const float*)d_in[6];
    const float* msgb = (const float*)d_in[7];
    const float* Wih  = (const float*)d_in[8];
    const float* Whh  = (const float*)d_in[9];
    const float* bih  = (const float*)d_in[10];
    const float* bhh  = (const float*)d_in[11];
    const float* pW   = (const float*)d_in[12];
    const float* pb   = (const float*)d_in[13];
    float* out = (float*)d_out;

    cudaFuncSetAttribute(k_neimma, cudaFuncAttributeMaxDynamicSharedMemorySize, NEI_SMEM);
    cudaFuncSetAttribute(k_msgru, cudaFuncAttributeMaxDynamicSharedMemorySize,
                         MSGRU_SMEM_BYTES);

    k_init<<<(N_BONDS * EMBED + 255) / 256, 256>>>(af, bf, atab, btab, out);
    k_convA<<<dim3(512, 8), 256>>>(adj);
    k_quant0<<<(32 * N_NODES) / 256, 256>>>();
    for (int d = 0; d < DEPTH; ++d) {
        k_neimma<<<dim3(64, 4), 256, NEI_SMEM>>>();
        k_msgru<<<N_NODES / 64, 256, MSGRU_SMEM_BYTES>>>(
            msgW + d * HIDDEN * 64, msgb + d * HIDDEN,
            Wih + d * 96 * HIDDEN, Whh + d * 96 * EMBED, bih + d * 96, bhh + d * 96);
    }
    k_pool<<<(N_NODES * EMBED + 255) / 256, 256>>>(bidx, out);
    k_graph<<<NUM_GRAPHS, HIDDEN>>>(pW, pb, out);
}

// round 6
// speedup vs baseline: 2.3735x; 2.3735x over previous
#include <cuda_runtime.h>
#include <cuda_fp16.h>
#include <math.h>
#include <stdint.h>

#define N_NODES 8192
#define N_BONDS 16384
#define EMBED 32
#define HIDDEN 256
#define DEPTH 10
#define NUM_GRAPHS 256

// ---------------- static device scratch ----------------
// A image: 4-bit {0,1}, fragment-ordered for mma.m16n8k16.f16.
// Block (mb 0..511, kc 0..63) = 1024B: [lane 32][kt 8][4B word].
//   word(kt) byte i (i=0..3): lo-nib = v(r, kk[i]), hi-nib = v(r+8, kk[i])
//   where r = lane>>2, k0 = kc*128 + kt*16 + (lane&3)*2, kk = {k0, k0+1, k0+8, k0+9}.
__device__ __align__(16) uint8_t g_A4[(size_t)512 * 64 * 1024];  // 32MB
__device__ __align__(16) __half g_hq[(size_t)N_NODES * EMBED];   // [j][e] fp16
__device__ __align__(16) float g_h[N_NODES * EMBED];
__device__ __align__(16) float g_neip[4][N_NODES * EMBED];       // [kq][node][e]
__device__ __align__(16) float g_Wc[DEPTH][96 * 64];             // composed Wih@Wmsg
__device__ float g_bc[DEPTH][96];                                // Wih@msg_b
__device__ float g_deg[N_NODES];
__device__ float g_pool_sum[NUM_GRAPHS * EMBED];
__device__ float g_pool_cnt[NUM_GRAPHS];

// ---------------- PTX helpers ----------------
__device__ __forceinline__ uint32_t smem_u32(const void* p) {
    uint32_t a;
    asm("{ .reg .u64 t; cvta.to.shared.u64 t, %1; cvt.u32.u64 %0, t; }" : "=r"(a) : "l"(p));
    return a;
}
__device__ __forceinline__ uint32_t prmt0(uint32_t a, uint32_t sel) {
    uint32_t d;
    asm("prmt.b32 %0, %1, 0, %2;" : "=r"(d) : "r"(a), "r"(sel));
    return d;
}
__device__ __forceinline__ void cp16(uint32_t dst, const void* src) {
    asm volatile("cp.async.cg.shared.global [%0], [%1], 16;" :: "r"(dst), "l"(src));
}
__device__ __forceinline__ void ldm_x4_trans(uint32_t* r, uint32_t addr) {
    asm volatile("ldmatrix.sync.aligned.m8n8.x4.trans.shared.b16 {%0,%1,%2,%3}, [%4];"
                 : "=r"(r[0]), "=r"(r[1]), "=r"(r[2]), "=r"(r[3]) : "r"(addr));
}
__device__ __forceinline__ void mma_f16(float* c, uint32_t a0, uint32_t a1,
                                        uint32_t a2, uint32_t a3,
                                        uint32_t b0, uint32_t b1) {
    asm volatile(
        "mma.sync.aligned.m16n8k16.row.col.f32.f16.f16.f32 "
        "{%0,%1,%2,%3}, {%4,%5,%6,%7}, {%8,%9}, {%0,%1,%2,%3};"
        : "+f"(c[0]), "+f"(c[1]), "+f"(c[2]), "+f"(c[3])
        : "r"(a0), "r"(a1), "r"(a2), "r"(a3), "r"(b0), "r"(b1));
}

// ---------------- init ----------------
__global__ void k_init(const int* __restrict__ af, const int* __restrict__ bf,
                       const float* __restrict__ atab, const float* __restrict__ btab,
                       float* __restrict__ out) {
    int idx = blockIdx.x * 256 + threadIdx.x;
    if (idx < N_BONDS * EMBED)
        out[N_NODES * EMBED + idx] = btab[bf[idx >> 5] * EMBED + (idx & 31)];
    if (idx < N_NODES * EMBED) {
        float h = atab[af[idx >> 5] * EMBED + (idx & 31)];
        g_h[idx] = h;
        g_hq[idx] = __float2half_rn(h);
    }
    if (idx < N_NODES) g_deg[idx] = 0.f;
    if (idx < NUM_GRAPHS * EMBED) g_pool_sum[idx] = 0.f;
    if (idx < NUM_GRAPHS) g_pool_cnt[idx] = 0.f;
}

// ---------------- adjacency -> 4-bit fragment-ordered image + degree ----------------
__global__ void __launch_bounds__(256) k_convA(const int* __restrict__ adj) {
    int t = threadIdx.x, lane = t & 31, w = t >> 5;
    int mb = blockIdx.x;
    int kc = blockIdx.y * 8 + w;
    int r = lane >> 2, kq = (lane & 3) * 2;
    int row0 = mb * 16;
    uint8_t* dst = g_A4 + (((size_t)mb * 64 + kc) * 1024) + (size_t)lane * 32;
    int cnt0 = 0, cnt8 = 0;
    uint32_t wv[8];
#pragma unroll
    for (int kt = 0; kt < 8; kt++) {
        int k0 = kc * 128 + kt * 16 + kq;
        int2 p00 = *(const int2*)&adj[(size_t)(row0 + r) * N_NODES + k0];
        int2 p08 = *(const int2*)&adj[(size_t)(row0 + r) * N_NODES + k0 + 8];
        int2 p80 = *(const int2*)&adj[(size_t)(row0 + r + 8) * N_NODES + k0];
        int2 p88 = *(const int2*)&adj[(size_t)(row0 + r + 8) * N_NODES + k0 + 8];
        uint32_t b0 = (p00.x != 0), b1 = (p00.y != 0);
        uint32_t b2 = (p08.x != 0), b3 = (p08.y != 0);
        uint32_t c0 = (p80.x != 0), c1 = (p80.y != 0);
        uint32_t c2 = (p88.x != 0), c3 = (p88.y != 0);
        cnt0 += b0 + b1 + b2 + b3;
        cnt8 += c0 + c1 + c2 + c3;
        wv[kt] = b0 | (c0 << 4) | (b1 << 8) | (c1 << 12) |
                 (b2 << 16) | (c2 << 20) | (b3 << 24) | (c3 << 28);
    }
    *(uint4*)(dst) = make_uint4(wv[0], wv[1], wv[2], wv[3]);
    *(uint4*)(dst + 16) = make_uint4(wv[4], wv[5], wv[6], wv[7]);
    cnt0 += __shfl_down_sync(0xffffffffu, cnt0, 2, 4);
    cnt0 += __shfl_down_sync(0xffffffffu, cnt0, 1, 4);
    cnt8 += __shfl_down_sync(0xffffffffu, cnt8, 2, 4);
    cnt8 += __shfl_down_sync(0xffffffffu, cnt8, 1, 4);
    if ((lane & 3) == 0) {
        atomicAdd(&g_deg[row0 + r], (float)cnt0);
        atomicAdd(&g_deg[row0 + r + 8], (float)cnt8);
    }
}

// ---------------- compose W_c = Wih @ Wmsg, b_c = Wih @ msg_b (all depths) ----------
__global__ void __launch_bounds__(256) k_compose(const float* __restrict__ msgW,
                                                 const float* __restrict__ msgb,
                                                 const float* __restrict__ Wih) {
    int d = blockIdx.x, q = blockIdx.y;
    int t = threadIdx.x;
    const float* Wd = msgW + (size_t)d * 256 * 64;
    const float* Wi = Wih + (size_t)d * 96 * 256;
    for (int idx = t; idx < 24 * 64; idx += 256) {
        int g = q * 24 + (idx >> 6), e = idx & 63;
        float acc = 0.f;
#pragma unroll 4
        for (int k = 0; k < 256; k++) acc = fmaf(Wi[g * 256 + k], Wd[k * 64 + e], acc);
        g_Wc[d][g * 64 + e] = acc;
    }
    if (q == 0 && t < 96) {
        float acc = 0.f;
        for (int k = 0; k < 256; k++) acc = fmaf(Wi[t * 256 + k], msgb[d * 256 + k], acc);
        g_bc[d][t] = acc;
    }
}

// ---------------- nei partials = A @ h_fp16 via mma.sync f16 (N=32) ----------------
// grid (64 mtiles, 4 kquarters), 256 threads = 8 warps (4m x 2n).
#define NEI_PITCH 80
#define NEI_STAGE_B (128 * NEI_PITCH)  // 10240
#define NEI_SMEM (4 * NEI_STAGE_B)
#define NEI_CHUNKS 16
#define NIBM 0x0F0F0F0Fu
__global__ void __launch_bounds__(256, 2) k_neimma() {
    extern __shared__ uint8_t smem[];
    uint32_t sb = smem_u32(smem);
    int t = threadIdx.x, lane = t & 31, w = t >> 5;
    int mw = w & 3, nw = w >> 2;
    int mtile = blockIdx.x, kq = blockIdx.y;

    const uint8_t* Abase = g_A4 +
        ((size_t)((mtile * 8 + mw * 2) * 64 + kq * 16)) * 1024 + (size_t)lane * 32;
    const uint8_t* Bbase = (const uint8_t*)g_hq + (size_t)kq * 2048 * 64;

#define LOADB(c, s)                                                             \
    {                                                                           \
        uint32_t dstb = sb + (s) * NEI_STAGE_B;                                 \
        const uint8_t* srcb = Bbase + (size_t)(c) * 128 * 64;                   \
        _Pragma("unroll")                                                       \
        for (int i = 0; i < 2; i++) {                                           \
            int idx = t + i * 256;                                              \
            int row = idx >> 2, cg = idx & 3;                                   \
            cp16(dstb + row * NEI_PITCH + cg * 16, srcb + row * 64 + cg * 16);  \
        }                                                                       \
        asm volatile("cp.async.commit_group;");                                 \
    }

    LOADB(0, 0);
    LOADB(1, 1);
    LOADB(2, 2);

    float acc[2][2][4];
#pragma unroll
    for (int mt = 0; mt < 2; mt++)
#pragma unroll
        for (int p = 0; p < 2; p++)
#pragma unroll
            for (int i = 0; i < 4; i++) acc[mt][p][i] = 0.f;

    int krb = lane & 15;
    int chi = lane >> 4;

    for (int c = 0; c < NEI_CHUNKS; c++) {
        uint4 aw[2][2];
#pragma unroll
        for (int mt = 0; mt < 2; mt++) {
            const uint4* p4 = (const uint4*)(Abase + (size_t)mt * 65536 + (size_t)c * 1024);
            aw[mt][0] = p4[0];
            aw[mt][1] = p4[1];
        }
        asm volatile("cp.async.wait_group 2;");
        __syncthreads();
        uint32_t sbase = sb + (c & 3) * NEI_STAGE_B;
#pragma unroll
        for (int kt = 0; kt < 8; kt++) {
            int krow = kt * 16 + krb;
            uint32_t bfr[4];
            ldm_x4_trans(bfr, sbase + krow * NEI_PITCH + (uint32_t)(nw * 2 + chi) * 16);
#pragma unroll
            for (int mt = 0; mt < 2; mt++) {
                uint4 q = aw[mt][kt >> 2];
                uint32_t wv = (kt & 2) ? ((kt & 1) ? q.w : q.z) : ((kt & 1) ? q.y : q.x);
                uint32_t lo = wv & NIBM;
                uint32_t hi = (wv >> 4) & NIBM;
                uint32_t a0 = prmt0(lo, 0x4140) * 0x3C00u;
                uint32_t a2 = prmt0(lo, 0x4342) * 0x3C00u;
                uint32_t a1 = prmt0(hi, 0x4140) * 0x3C00u;
                uint32_t a3 = prmt0(hi, 0x4342) * 0x3C00u;
                mma_f16(acc[mt][0], a0, a1, a2, a3, bfr[0], bfr[1]);
                mma_f16(acc[mt][1], a0, a1, a2, a3, bfr[2], bfr[3]);
            }
        }
        __syncthreads();
        if (c + 3 < NEI_CHUNKS) LOADB(c + 3, (c + 3) & 3);
    }

    float* base = g_neip[kq];
    int r = lane >> 2, c0 = (lane & 3) * 2;
#pragma unroll
    for (int mt = 0; mt < 2; mt++) {
        int node0 = (mtile * 8 + mw * 2 + mt) * 16 + r;
#pragma unroll
        for (int p = 0; p < 2; p++) {
            int col = nw * 16 + p * 8 + c0;
            *(float2*)&base[(size_t)node0 * 32 + col] =
                make_float2(acc[mt][p][0], acc[mt][p][1]);
            *(float2*)&base[(size_t)(node0 + 8) * 32 + col] =
                make_float2(acc[mt][p][2], acc[mt][p][3]);
        }
    }
#undef LOADB
}

// ---------------- fused (composed msg+GRU) + fp16 requant ----------------
// gi = bih + hasnei * (x @ W_c^T + b_c);  gh = h @ Whh^T + bhh
#define MSGRU_SMEM_FLOATS (64 * 68 + 64 * 100 + 32 * 100)
__global__ void __launch_bounds__(256) k_msgru(int d,
                                               const float* __restrict__ Whh,
                                               const float* __restrict__ bih,
                                               const float* __restrict__ bhh) {
    extern __shared__ float sm[];
    float* x_s = sm;                   // [64 nodes][68] : h(32) | nei_mean(32)
    float* wc_s = x_s + 64 * 68;       // [k=64][g pitch 100]
    float* whh_s = wc_s + 64 * 100;    // [k=32][g pitch 100]
    int row0 = blockIdx.x * 64;
    int t = threadIdx.x;
    const float* Wc = g_Wc[d];
    const float* bc = g_bc[d];
    const float* bihd = bih + d * 96;
    const float* bhhd = bhh + d * 96;
    const float* Whhd = Whh + (size_t)d * 96 * 32;

    for (int idx = t; idx < 64 * EMBED; idx += 256) {
        int r = idx >> 5, e = idx & 31;
        int node = row0 + r;
        float invd = 1.0f / fmaxf(g_deg[node], 1.0f);
        int o = node * 32 + e;
        float s = g_neip[0][o] + g_neip[1][o] + g_neip[2][o] + g_neip[3][o];
        x_s[r * 68 + e] = g_h[o];
        x_s[r * 68 + 32 + e] = s * invd;
    }
    for (int idx = t; idx < 96 * 64; idx += 256) {
        int g = idx >> 6, k = idx & 63;
        wc_s[k * 100 + g] = Wc[idx];
    }
    for (int idx = t; idx < 96 * EMBED; idx += 256) {
        int g = idx >> 5, k = idx & 31;
        whh_s[k * 100 + g] = Whhd[idx];
    }
    __syncthreads();

    int e = t & 31;
    int rb = (t >> 5) * 8;
    float gi[8][3], gh[8][3];
#pragma unroll
    for (int i = 0; i < 8; i++) {
        gi[i][0] = gi[i][1] = gi[i][2] = 0.f;
        gh[i][0] = gh[i][1] = gh[i][2] = 0.f;
    }
    for (int k = 0; k < 64; k++) {
        float w0 = wc_s[k * 100 + e];
        float w1 = wc_s[k * 100 + 32 + e];
        float w2 = wc_s[k * 100 + 64 + e];
#pragma unroll
        for (int i = 0; i < 8; i++) {
            float x = x_s[(rb + i) * 68 + k];
            gi[i][0] = fmaf(x, w0, gi[i][0]);
            gi[i][1] = fmaf(x, w1, gi[i][1]);
            gi[i][2] = fmaf(x, w2, gi[i][2]);
        }
    }
    for (int k = 0; k < EMBED; k++) {
        float w0 = whh_s[k * 100 + e];
        float w1 = whh_s[k * 100 + 32 + e];
        float w2 = whh_s[k * 100 + 64 + e];
#pragma unroll
        for (int i = 0; i < 8; i++) {
            float hv = x_s[(rb + i) * 68 + k];
            gh[i][0] = fmaf(hv, w0, gh[i][0]);
            gh[i][1] = fmaf(hv, w1, gh[i][1]);
            gh[i][2] = fmaf(hv, w2, gh[i][2]);
        }
    }
    float bc0 = bc[e], bc1 = bc[32 + e], bc2 = bc[64 + e];
    float bi0 = bihd[e], bi1 = bihd[32 + e], bi2 = bihd[64 + e];
    float bh0 = bhhd[e], bh1 = bhhd[32 + e], bh2 = bhhd[64 + e];
#pragma unroll
    for (int i = 0; i < 8; i++) {
        int node = row0 + rb + i;
        float hn = g_deg[node] > 0.f ? 1.f : 0.f;
        float ir = bi0 + hn * (gi[i][0] + bc0);
        float iz = bi1 + hn * (gi[i][1] + bc1);
        float in_ = bi2 + hn * (gi[i][2] + bc2);
        float rg = 1.f / (1.f + expf(-(ir + (gh[i][0] + bh0))));
        float z  = 1.f / (1.f + expf(-(iz + (gh[i][1] + bh1))));
        float n  = tanhf(in_ + rg * (gh[i][2] + bh2));
        float hp = x_s[(rb + i) * 68 + e];
        float hnew = (1.f - z) * n + z * hp;
        g_h[(size_t)node * EMBED + e] = hnew;
        g_hq[(size_t)node * EMBED + e] = __float2half_rn(hnew);
    }
}

// ---------------- pooling ----------------
__global__ void k_pool(const int* __restrict__ bidx, float* __restrict__ out) {
    int idx = blockIdx.x * 256 + threadIdx.x;
    if (idx < N_NODES * EMBED) {
        int n = idx >> 5, e = idx & 31;
        float v = g_h[idx];
        out[idx] = v;
        int b = bidx[n];
        atomicAdd(&g_pool_sum[b * EMBED + e], v);
        if (e == 0) atomicAdd(&g_pool_cnt[b], 1.0f);
    }
}

__global__ void __launch_bounds__(256) k_graph(const float* __restrict__ pW,
                                               const float* __restrict__ pb,
                                               float* __restrict__ out) {
    __shared__ float mean[EMBED];
    __shared__ float Ws[EMBED * HIDDEN];
    int b = blockIdx.x;
    int t = threadIdx.x;
    for (int idx = t; idx < HIDDEN * EMBED; idx += 256) {
        int o = idx >> 5, e = idx & 31;
        Ws[e * HIDDEN + o] = pW[idx];
    }
    if (t < EMBED) {
        float cnt = g_pool_cnt[b];
        mean[t] = cnt > 0.f ? g_pool_sum[b * EMBED + t] / cnt : 0.f;
    }
    __syncthreads();
    float acc = pb[t];
#pragma unroll
    for (int e = 0; e < EMBED; e++) acc = fmaf(mean[e], Ws[e * HIDDEN + t], acc);
    out[(size_t)(N_NODES * EMBED + N_BONDS * EMBED) + b * HIDDEN + t] = acc;
}

// ---------------- launch ----------------
extern "C" void kernel_launch(void* const* d_in, const int* in_sizes, int n_in,
                              void* d_out, int out_size) {
    const int* af    = (const int*)d_in[0];
    const int* bf    = (const int*)d_in[1];
    const int* adj   = (const int*)d_in[2];
    const int* bidx  = (const int*)d_in[3];
    const float* atab = (const float*)d_in[4];
    const float* btab = (const float*)d_in[5];
    const float* msgW = (const float*)d_in[6];
    const float* msgb = (const float*)d_in[7];
    const float* Wih  = (const float*)d_in[8];
    const float* Whh  = (const float*)d_in[9];
    const float* bih  = (const float*)d_in[10];
    const float* bhh  = (const float*)d_in[11];
    const float* pW   = (const float*)d_in[12];
    const float* pb   = (const float*)d_in[13];
    float* out = (float*)d_out;

    cudaFuncSetAttribute(k_neimma, cudaFuncAttributeMaxDynamicSharedMemorySize, NEI_SMEM);
    cudaFuncSetAttribute(k_msgru, cudaFuncAttributeMaxDynamicSharedMemorySize,
                         MSGRU_SMEM_FLOATS * 4);

    k_init<<<(N_BONDS * EMBED + 255) / 256, 256>>>(af, bf, atab, btab, out);
    k_convA<<<dim3(512, 8), 256>>>(adj);
    k_compose<<<dim3(DEPTH, 4), 256>>>(msgW, msgb, Wih);
    for (int d = 0; d < DEPTH; ++d) {
        k_neimma<<<dim3(64, 4), 256, NEI_SMEM>>>();
        k_msgru<<<N_NODES / 64, 256, MSGRU_SMEM_FLOATS * 4>>>(d, Whh, bih, bhh);
    }
    k_pool<<<(N_NODES * EMBED + 255) / 256, 256>>>(bidx, out);
    k_graph<<<NUM_GRAPHS, HIDDEN>>>(pW, pb, out);
}